// round 9
// baseline (speedup 1.0000x reference)
#include <cuda_runtime.h>
#include <cuda_fp16.h>
#include <cuda_bf16.h>

#define LRES 128
#define HRES 1024
#define NCH 8
#define LBLK (LRES / 2)     // 64 grid blocks per axis
#define HBLK (HRES / 2)     // 512 plane blocks per axis

// Channel-innermost fp16 scratch, Morton-within-line blocked.
// Grid: 2x2x2 texel blocks, one block = 8*16B = 128B = one cache line.
// Planes: 2x2 texel blocks = 64B; two W-adjacent blocks share one line.
__device__ __half g_grid_h[LRES * LRES * LRES * NCH];    // 32 MB
__device__ __half g_planes_h[3 * HRES * HRES * NCH];     // 48 MB

__device__ __forceinline__ uint4 pack8_half(float4 a, float4 b) {
    union { uint4 u; __half2 h[4]; } r;
    r.h[0] = __floats2half2_rn(a.x, a.y);
    r.h[1] = __floats2half2_rn(a.z, a.w);
    r.h[2] = __floats2half2_rn(b.x, b.y);
    r.h[3] = __floats2half2_rn(b.z, b.w);
    return r.u;
}

// Blocked texel index for grid (z,y,x) -> uint4 slot.
__device__ __forceinline__ int gidx_blk(int z, int y, int x) {
    int B = ((z >> 1) * LBLK + (y >> 1)) * LBLK + (x >> 1);
    return B * 8 + ((z & 1) << 2) + ((y & 1) << 1) + (x & 1);
}
// Blocked texel index for plane p, (h,w) -> uint4 slot.
__device__ __forceinline__ int pidx_blk(int p, int h, int w) {
    int B = (h >> 1) * HBLK + (w >> 1);
    return p * (HRES * HRES) + B * 4 + ((h & 1) << 1) + (w & 1);
}

// ---------------------------------------------------------------------------
// Fused transpose: 1 texel/thread (low regs, BW-bound), blocked output.
//   threads [0, VG)         : grid  [C,D,H,W] fp32 -> blocked [z,y,x,c] fp16
//   threads [VG, VG + 3*V2) : planes [3,C,H,W] fp32 -> blocked [p,h,w,c] fp16
// ---------------------------------------------------------------------------
__global__ void __launch_bounds__(256) transpose_all_kernel(
    const float* __restrict__ grid_in,
    const float* __restrict__ planes_in)
{
    const int VG = LRES * LRES * LRES;
    const int V2 = HRES * HRES;
    int t = blockIdx.x * blockDim.x + threadIdx.x;

    if (t < VG) {
        int v = t;
        float4 a, b;
        a.x = __ldg(grid_in + 0 * VG + v);
        a.y = __ldg(grid_in + 1 * VG + v);
        a.z = __ldg(grid_in + 2 * VG + v);
        a.w = __ldg(grid_in + 3 * VG + v);
        b.x = __ldg(grid_in + 4 * VG + v);
        b.y = __ldg(grid_in + 5 * VG + v);
        b.z = __ldg(grid_in + 6 * VG + v);
        b.w = __ldg(grid_in + 7 * VG + v);
        int x = v & (LRES - 1);
        int y = (v >> 7) & (LRES - 1);
        int z = v >> 14;
        reinterpret_cast<uint4*>(g_grid_h)[gidx_blk(z, y, x)] = pack8_half(a, b);
    } else {
        int u = t - VG;
        if (u >= 3 * V2) return;
        int p = u / V2;
        int v = u - p * V2;
        const float* base = planes_in + (size_t)p * NCH * V2 + v;
        float4 a, b;
        a.x = __ldg(base + 0 * V2);
        a.y = __ldg(base + 1 * V2);
        a.z = __ldg(base + 2 * V2);
        a.w = __ldg(base + 3 * V2);
        b.x = __ldg(base + 4 * V2);
        b.y = __ldg(base + 5 * V2);
        b.z = __ldg(base + 6 * V2);
        b.w = __ldg(base + 7 * V2);
        int w = v & (HRES - 1);
        int h = v >> 10;
        reinterpret_cast<uint4*>(g_planes_h)[pidx_blk(p, h, w)] = pack8_half(a, b);
    }
}

// ---------------------------------------------------------------------------
// Pair-lane gather: lanes (2i, 2i+1) share point i; lane r handles the
// W-dimension index x_r. 10 LDG.128 per lane into blocked layouts,
// half-exchange via 4 SHFL.BFLY, contiguous 16B store per lane.
// ---------------------------------------------------------------------------
__device__ __forceinline__ void to_idx(float c, int size, int& i0, int& i1, float& w) {
    // align_corners=True mapping; w from UNCLIPPED floor (matches ref).
    float p = (c + 1.0f) * 0.5f * (float)(size - 1);
    float f = floorf(p);
    w = p - f;
    int i = (int)f;
    i0 = min(max(i, 0), size - 1);
    i1 = min(i0 + 1, size - 1);
}

__device__ __forceinline__ void acc_texel(float* acc, uint4 v, float w) {
    union { uint4 u; __half2 h[4]; } r; r.u = v;
    float2 f0 = __half22float2(r.h[0]);
    float2 f1 = __half22float2(r.h[1]);
    float2 f2 = __half22float2(r.h[2]);
    float2 f3 = __half22float2(r.h[3]);
    acc[0] = fmaf(w, f0.x, acc[0]); acc[1] = fmaf(w, f0.y, acc[1]);
    acc[2] = fmaf(w, f1.x, acc[2]); acc[3] = fmaf(w, f1.y, acc[3]);
    acc[4] = fmaf(w, f2.x, acc[4]); acc[5] = fmaf(w, f2.y, acc[5]);
    acc[6] = fmaf(w, f3.x, acc[6]); acc[7] = fmaf(w, f3.y, acc[7]);
}

__global__ void __launch_bounds__(256) gather_kernel(
    const float* __restrict__ xyz,
    const int* __restrict__ bound_p,
    float* __restrict__ out,
    int N)
{
    int tid = blockIdx.x * blockDim.x + threadIdx.x;
    int n = tid >> 1;            // point index (2 lanes per point)
    int r = tid & 1;             // 0: low W index, 1: high W index
    if (n >= N) return;

    int bi = __ldg(bound_p);
    float bound = (bi > 0 && bi < 100000000) ? (float)bi : __int_as_float(bi);
    float inv = 1.0f / bound;

    float x = __ldg(xyz + 3 * n + 0) * inv;
    float y = __ldg(xyz + 3 * n + 1) * inv;
    float z = __ldg(xyz + 3 * n + 2) * inv;

    const uint4* GT = reinterpret_cast<const uint4*>(g_grid_h);
    const uint4* PT = reinterpret_cast<const uint4*>(g_planes_h);

    // ---- index math (both lanes compute identically) ----
    int x0, x1, y0, y1, z0, z1;
    float wx, wy, wz;
    to_idx(x, LRES, x0, x1, wx);
    to_idx(y, LRES, y0, y1, wy);
    to_idx(z, LRES, z0, z1, wz);

    int xh0, xh1, yh0, yh1, zh0, zh1;
    float wxh, wyh, wzh;
    to_idx(x, HRES, xh0, xh1, wxh);
    to_idx(y, HRES, yh0, yh1, wyh);
    to_idx(z, HRES, zh0, zh1, wzh);

    // lane-specific W-dim picks + weights
    int   gx  = r ? x1  : x0;   float wgx = r ? wx  : 1.0f - wx;
    int   p0x = r ? xh1 : xh0;  float w0x = r ? wxh : 1.0f - wxh;  // plane0 W = x
    int   p1y = r ? yh1 : yh0;  float w1y = r ? wyh : 1.0f - wyh;  // plane1 W = y
    int   p2z = r ? zh1 : zh0;  float w2z = r ? wzh : 1.0f - wzh;  // plane2 W = z

    // ---- 10 loads, batched for MLP ----
    uint4 g00 = __ldg(GT + gidx_blk(z0, y0, gx));
    uint4 g01 = __ldg(GT + gidx_blk(z0, y1, gx));
    uint4 g10 = __ldg(GT + gidx_blk(z1, y0, gx));
    uint4 g11 = __ldg(GT + gidx_blk(z1, y1, gx));
    uint4 pa0 = __ldg(PT + pidx_blk(0, yh0, p0x));
    uint4 pa1 = __ldg(PT + pidx_blk(0, yh1, p0x));
    uint4 pb0 = __ldg(PT + pidx_blk(1, zh0, p1y));
    uint4 pb1 = __ldg(PT + pidx_blk(1, zh1, p1y));
    uint4 pc0 = __ldg(PT + pidx_blk(2, xh0, p2z));
    uint4 pc1 = __ldg(PT + pidx_blk(2, xh1, p2z));

    // ---- accumulate fp32 (half the corners; pair exchange completes it) ----
    float acc[NCH];
#pragma unroll
    for (int c = 0; c < NCH; c++) acc[c] = 0.0f;

    {
        float uy = 1.0f - wy, uz = 1.0f - wz;
        acc_texel(acc, g00, uz * uy * wgx);
        acc_texel(acc, g01, uz * wy * wgx);
        acc_texel(acc, g10, wz * uy * wgx);
        acc_texel(acc, g11, wz * wy * wgx);
    }
    acc_texel(acc, pa0, (1.0f - wyh) * w0x);   // plane0: H = y
    acc_texel(acc, pa1, wyh * w0x);
    acc_texel(acc, pb0, (1.0f - wzh) * w1y);   // plane1: H = z
    acc_texel(acc, pb1, wzh * w1y);
    acc_texel(acc, pc0, (1.0f - wxh) * w2z);   // plane2: H = x
    acc_texel(acc, pc1, wxh * w2z);

    // ---- half exchange: 4 SHFLs. Each lane sends the half it doesn't keep.
    unsigned mask = __activemask();
    float res[4];
#pragma unroll
    for (int c = 0; c < 4; c++) {
        float keep = r ? acc[c + 4] : acc[c];
        float send = r ? acc[c]     : acc[c + 4];
        float recv = __shfl_xor_sync(mask, send, 1);
        res[c] = keep + recv;
    }

    // ---- store: lane r writes float4 #r of point n -> fully contiguous ----
    reinterpret_cast<float4*>(out)[(size_t)n * 2 + r] =
        make_float4(res[0], res[1], res[2], res[3]);
}

extern "C" void kernel_launch(void* const* d_in, const int* in_sizes, int n_in,
                              void* d_out, int out_size) {
    const float* xyz   = (const float*)d_in[0];
    const int*   bound = (const int*)d_in[1];
    const float* Lg    = (const float*)d_in[2];
    const float* Hp    = (const float*)d_in[3];
    float* out = (float*)d_out;

    int N = in_sizes[0] / 3;

    const int VG = LRES * LRES * LRES;
    const int VT = VG + 3 * HRES * HRES;
    transpose_all_kernel<<<(VT + 255) / 256, 256>>>(Lg, Hp);

    int threads = 2 * N;
    gather_kernel<<<(threads + 255) / 256, 256>>>(xyz, bound, out, N);
}

// round 10
// speedup vs baseline: 1.0567x; 1.0567x over previous
#include <cuda_runtime.h>
#include <cuda_fp16.h>
#include <cuda_bf16.h>

#define LRES 128
#define HRES 1024
#define NCH 8

// Channel-innermost fp16 scratch (LINEAR layouts — R8 proven best for
// per-instruction pair-lane line sharing). One texel = 16B = one LDG.128.
__device__ __half g_grid_h[LRES * LRES * LRES * NCH];    // [z][y][x][c]  32 MB
__device__ __half g_planes_h[3 * HRES * HRES * NCH];     // [p][h][w][c]  48 MB

__device__ __forceinline__ uint4 pack8_half(float4 a, float4 b) {
    union { uint4 u; __half2 h[4]; } r;
    r.h[0] = __floats2half2_rn(a.x, a.y);
    r.h[1] = __floats2half2_rn(a.z, a.w);
    r.h[2] = __floats2half2_rn(b.x, b.y);
    r.h[3] = __floats2half2_rn(b.z, b.w);
    return r.u;
}

__device__ __forceinline__ void to_idx(float c, int size, int& i0, int& i1, float& w) {
    // align_corners=True mapping; w from UNCLIPPED floor (matches ref).
    float p = (c + 1.0f) * 0.5f * (float)(size - 1);
    float f = floorf(p);
    w = p - f;
    int i = (int)f;
    i0 = min(max(i, 0), size - 1);
    i1 = min(i0 + 1, size - 1);
}

__device__ __forceinline__ void acc_texel(float* acc, uint4 v, float w) {
    union { uint4 u; __half2 h[4]; } r; r.u = v;
    float2 f0 = __half22float2(r.h[0]);
    float2 f1 = __half22float2(r.h[1]);
    float2 f2 = __half22float2(r.h[2]);
    float2 f3 = __half22float2(r.h[3]);
    acc[0] = fmaf(w, f0.x, acc[0]); acc[1] = fmaf(w, f0.y, acc[1]);
    acc[2] = fmaf(w, f1.x, acc[2]); acc[3] = fmaf(w, f1.y, acc[3]);
    acc[4] = fmaf(w, f2.x, acc[4]); acc[5] = fmaf(w, f2.y, acc[5]);
    acc[6] = fmaf(w, f3.x, acc[6]); acc[7] = fmaf(w, f3.y, acc[7]);
}

__device__ __forceinline__ float get_bound(const int* bound_p) {
    int bi = __ldg(bound_p);
    return (bi > 0 && bi < 100000000) ? (float)bi : __int_as_float(bi);
}

// ---------------------------------------------------------------------------
// K1: transpose grid [C,D,H,W] fp32 -> [D,H,W,C] fp16. 1 texel/thread.
// ---------------------------------------------------------------------------
__global__ void __launch_bounds__(256) transpose_grid_kernel(const float* __restrict__ in) {
    const int V = LRES * LRES * LRES;
    int v = blockIdx.x * blockDim.x + threadIdx.x;
    if (v >= V) return;
    float4 a, b;
    a.x = __ldg(in + 0 * V + v);
    a.y = __ldg(in + 1 * V + v);
    a.z = __ldg(in + 2 * V + v);
    a.w = __ldg(in + 3 * V + v);
    b.x = __ldg(in + 4 * V + v);
    b.y = __ldg(in + 5 * V + v);
    b.z = __ldg(in + 6 * V + v);
    b.w = __ldg(in + 7 * V + v);
    reinterpret_cast<uint4*>(g_grid_h)[v] = pack8_half(a, b);
}

// ---------------------------------------------------------------------------
// K2: fused — interleaved block roles:
//   role 0: GRID gather (pair-lane, 4 LDG.128/lane), writes grid partial to out
//   role 1: PLANES transpose [3,C,H,W] fp32 -> [3][H][W][C] fp16
// Interleave (bid & 1) keeps both types resident every wave: the DRAM-bound
// transpose and the L1tex-bound gather overlap on disjoint resources.
// ---------------------------------------------------------------------------
__global__ void __launch_bounds__(256) fused_planes_gridgather_kernel(
    const float* __restrict__ planes_in,
    const float* __restrict__ xyz,
    const int* __restrict__ bound_p,
    float* __restrict__ out,
    int N, int TB, int GB)
{
    int bid = blockIdx.x;
    int role, idx;
    int m = TB < GB ? TB : GB;
    if (bid < 2 * m) {
        role = bid & 1;          // even -> gather, odd -> transpose
        idx = bid >> 1;
    } else if (GB > TB) {
        role = 0; idx = bid - TB;
    } else {
        role = 1; idx = bid - GB;
    }

    if (role == 1) {
        // ---- planes transpose ----
        const int V2 = HRES * HRES;
        int u = idx * 256 + threadIdx.x;
        if (u >= 3 * V2) return;
        int p = u / V2;
        int v = u - p * V2;
        const float* base = planes_in + (size_t)p * NCH * V2 + v;
        float4 a, b;
        a.x = __ldg(base + 0 * V2);
        a.y = __ldg(base + 1 * V2);
        a.z = __ldg(base + 2 * V2);
        a.w = __ldg(base + 3 * V2);
        b.x = __ldg(base + 4 * V2);
        b.y = __ldg(base + 5 * V2);
        b.z = __ldg(base + 6 * V2);
        b.w = __ldg(base + 7 * V2);
        reinterpret_cast<uint4*>(g_planes_h)[u] = pack8_half(a, b);
        return;
    }

    // ---- grid gather (pair-lane) ----
    int tid = idx * 256 + threadIdx.x;
    int n = tid >> 1;
    int r = tid & 1;
    if (n >= N) return;

    float inv = 1.0f / get_bound(bound_p);
    float x = __ldg(xyz + 3 * n + 0) * inv;
    float y = __ldg(xyz + 3 * n + 1) * inv;
    float z = __ldg(xyz + 3 * n + 2) * inv;

    int x0, x1, y0, y1, z0, z1;
    float wx, wy, wz;
    to_idx(x, LRES, x0, x1, wx);
    to_idx(y, LRES, y0, y1, wy);
    to_idx(z, LRES, z0, z1, wz);

    int   gx  = r ? x1 : x0;
    float wgx = r ? wx : 1.0f - wx;

    const uint4* GT = reinterpret_cast<const uint4*>(g_grid_h);
    #define GIDX(zz, yy) (((zz) * LRES + (yy)) * LRES + gx)
    uint4 g00 = __ldg(GT + GIDX(z0, y0));
    uint4 g01 = __ldg(GT + GIDX(z0, y1));
    uint4 g10 = __ldg(GT + GIDX(z1, y0));
    uint4 g11 = __ldg(GT + GIDX(z1, y1));
    #undef GIDX

    float acc[NCH];
#pragma unroll
    for (int c = 0; c < NCH; c++) acc[c] = 0.0f;
    float uy = 1.0f - wy, uz = 1.0f - wz;
    acc_texel(acc, g00, uz * uy * wgx);
    acc_texel(acc, g01, uz * wy * wgx);
    acc_texel(acc, g10, wz * uy * wgx);
    acc_texel(acc, g11, wz * wy * wgx);

    // half exchange: each lane sends the half it doesn't keep
    unsigned mask = __activemask();
    float res[4];
#pragma unroll
    for (int c = 0; c < 4; c++) {
        float keep = r ? acc[c + 4] : acc[c];
        float send = r ? acc[c]     : acc[c + 4];
        res[c] = keep + __shfl_xor_sync(mask, send, 1);
    }
    reinterpret_cast<float4*>(out)[(size_t)n * 2 + r] =
        make_float4(res[0], res[1], res[2], res[3]);
}

// ---------------------------------------------------------------------------
// K3: plane gather (pair-lane, 6 LDG.128/lane) + accumulate into out.
// ---------------------------------------------------------------------------
__global__ void __launch_bounds__(256) gather_planes_kernel(
    const float* __restrict__ xyz,
    const int* __restrict__ bound_p,
    float* __restrict__ out,
    int N)
{
    int tid = blockIdx.x * blockDim.x + threadIdx.x;
    int n = tid >> 1;
    int r = tid & 1;
    if (n >= N) return;

    float inv = 1.0f / get_bound(bound_p);
    float x = __ldg(xyz + 3 * n + 0) * inv;
    float y = __ldg(xyz + 3 * n + 1) * inv;
    float z = __ldg(xyz + 3 * n + 2) * inv;

    int xh0, xh1, yh0, yh1, zh0, zh1;
    float wxh, wyh, wzh;
    to_idx(x, HRES, xh0, xh1, wxh);
    to_idx(y, HRES, yh0, yh1, wyh);
    to_idx(z, HRES, zh0, zh1, wzh);

    int   p0x = r ? xh1 : xh0;  float w0x = r ? wxh : 1.0f - wxh;  // plane0 W = x
    int   p1y = r ? yh1 : yh0;  float w1y = r ? wyh : 1.0f - wyh;  // plane1 W = y
    int   p2z = r ? zh1 : zh0;  float w2z = r ? wzh : 1.0f - wzh;  // plane2 W = z

    const uint4* PT = reinterpret_cast<const uint4*>(g_planes_h);
    #define PIDX(p, hh, ww) ((p) * (HRES * HRES) + (hh) * HRES + (ww))
    uint4 pa0 = __ldg(PT + PIDX(0, yh0, p0x));
    uint4 pa1 = __ldg(PT + PIDX(0, yh1, p0x));
    uint4 pb0 = __ldg(PT + PIDX(1, zh0, p1y));
    uint4 pb1 = __ldg(PT + PIDX(1, zh1, p1y));
    uint4 pc0 = __ldg(PT + PIDX(2, xh0, p2z));
    uint4 pc1 = __ldg(PT + PIDX(2, xh1, p2z));
    #undef PIDX

    // load grid partial early (coalesced, overlaps with texel loads)
    float4 prev = reinterpret_cast<const float4*>(out)[(size_t)n * 2 + r];

    float acc[NCH];
#pragma unroll
    for (int c = 0; c < NCH; c++) acc[c] = 0.0f;
    acc_texel(acc, pa0, (1.0f - wyh) * w0x);   // plane0: H = y
    acc_texel(acc, pa1, wyh * w0x);
    acc_texel(acc, pb0, (1.0f - wzh) * w1y);   // plane1: H = z
    acc_texel(acc, pb1, wzh * w1y);
    acc_texel(acc, pc0, (1.0f - wxh) * w2z);   // plane2: H = x
    acc_texel(acc, pc1, wxh * w2z);

    unsigned mask = __activemask();
    float res[4];
#pragma unroll
    for (int c = 0; c < 4; c++) {
        float keep = r ? acc[c + 4] : acc[c];
        float send = r ? acc[c]     : acc[c + 4];
        res[c] = keep + __shfl_xor_sync(mask, send, 1);
    }
    reinterpret_cast<float4*>(out)[(size_t)n * 2 + r] =
        make_float4(res[0] + prev.x, res[1] + prev.y,
                    res[2] + prev.z, res[3] + prev.w);
}

extern "C" void kernel_launch(void* const* d_in, const int* in_sizes, int n_in,
                              void* d_out, int out_size) {
    const float* xyz   = (const float*)d_in[0];
    const int*   bound = (const int*)d_in[1];
    const float* Lg    = (const float*)d_in[2];
    const float* Hp    = (const float*)d_in[3];
    float* out = (float*)d_out;

    int N = in_sizes[0] / 3;

    // K1: grid transpose
    const int VG = LRES * LRES * LRES;
    transpose_grid_kernel<<<VG / 256, 256>>>(Lg);

    // K2: planes transpose (TB blocks) interleaved with grid gather (GB blocks)
    const int TB = (3 * HRES * HRES + 255) / 256;
    const int GB = (2 * N + 255) / 256;
    fused_planes_gridgather_kernel<<<TB + GB, 256>>>(Hp, xyz, bound, out, N, TB, GB);

    // K3: plane gather + accumulate
    gather_planes_kernel<<<GB, 256>>>(xyz, bound, out, N);
}

// round 12
// speedup vs baseline: 1.1964x; 1.1322x over previous
#include <cuda_runtime.h>
#include <cuda_fp16.h>
#include <cuda_bf16.h>

#define LRES 128
#define HRES 1024
#define NCH 8

// Channel-innermost fp16 scratch (LINEAR layouts — proven best for
// per-instruction pair-lane line sharing). One texel = 16B = one LDG.128.
__device__ __half g_grid_h[LRES * LRES * LRES * NCH];    // [z][y][x][c]  32 MB
__device__ __half g_planes_h[3 * HRES * HRES * NCH];     // [p][h][w][c]  48 MB

// bbox of xyz (order-preserving uint encoding of float)
__device__ unsigned g_bbox_min[3];
__device__ unsigned g_bbox_max[3];

__device__ __forceinline__ unsigned f2u_ord(float f) {
    unsigned u = __float_as_uint(f);
    return (u & 0x80000000u) ? ~u : (u | 0x80000000u);
}
__device__ __forceinline__ float u2f_ord(unsigned u) {
    return __uint_as_float((u & 0x80000000u) ? (u ^ 0x80000000u) : ~u);
}

__device__ __forceinline__ uint4 pack8_half(float4 a, float4 b) {
    union { uint4 u; __half2 h[4]; } r;
    r.h[0] = __floats2half2_rn(a.x, a.y);
    r.h[1] = __floats2half2_rn(a.z, a.w);
    r.h[2] = __floats2half2_rn(b.x, b.y);
    r.h[3] = __floats2half2_rn(b.z, b.w);
    return r.u;
}

__device__ __forceinline__ void to_idx(float c, int size, int& i0, int& i1, float& w) {
    // align_corners=True mapping; w from UNCLIPPED floor (matches ref).
    float p = (c + 1.0f) * 0.5f * (float)(size - 1);
    float f = floorf(p);
    w = p - f;
    int i = (int)f;
    i0 = min(max(i, 0), size - 1);
    i1 = min(i0 + 1, size - 1);
}

__device__ __forceinline__ void acc_texel(float* acc, uint4 v, float w) {
    union { uint4 u; __half2 h[4]; } r; r.u = v;
    float2 f0 = __half22float2(r.h[0]);
    float2 f1 = __half22float2(r.h[1]);
    float2 f2 = __half22float2(r.h[2]);
    float2 f3 = __half22float2(r.h[3]);
    acc[0] = fmaf(w, f0.x, acc[0]); acc[1] = fmaf(w, f0.y, acc[1]);
    acc[2] = fmaf(w, f1.x, acc[2]); acc[3] = fmaf(w, f1.y, acc[3]);
    acc[4] = fmaf(w, f2.x, acc[4]); acc[5] = fmaf(w, f2.y, acc[5]);
    acc[6] = fmaf(w, f3.x, acc[6]); acc[7] = fmaf(w, f3.y, acc[7]);
}

__device__ __forceinline__ float get_bound(const int* bound_p) {
    int bi = __ldg(bound_p);
    return (bi > 0 && bi < 100000000) ? (float)bi : __int_as_float(bi);
}

// index range [lo, hi] of texels touchable by normalized coords in [cmin, cmax]
__device__ __forceinline__ void coord_range(float cmin, float cmax, int S,
                                            int& lo, int& hi) {
    float pmin = (cmin + 1.0f) * 0.5f * (float)(S - 1);
    float pmax = (cmax + 1.0f) * 0.5f * (float)(S - 1);
    lo = max((int)floorf(pmin) - 1, 0);
    hi = min((int)floorf(pmax) + 2, S - 1);
}

// ---------------------------------------------------------------------------
// K0: reset bbox
// ---------------------------------------------------------------------------
__global__ void bbox_init_kernel() {
    if (threadIdx.x < 3) {
        g_bbox_min[threadIdx.x] = 0xFFFFFFFFu;
        g_bbox_max[threadIdx.x] = 0u;
    }
}

// ---------------------------------------------------------------------------
// K1: bbox reduction over xyz (grid-stride, warp-reduce, per-warp atomics)
// ---------------------------------------------------------------------------
__global__ void __launch_bounds__(256) bbox_kernel(const float* __restrict__ xyz, int N) {
    float mn[3] = { 1e30f,  1e30f,  1e30f};
    float mx[3] = {-1e30f, -1e30f, -1e30f};
    int stride = gridDim.x * blockDim.x;
    for (int n = blockIdx.x * blockDim.x + threadIdx.x; n < N; n += stride) {
#pragma unroll
        for (int d = 0; d < 3; d++) {
            float v = __ldg(xyz + 3 * n + d);
            mn[d] = fminf(mn[d], v);
            mx[d] = fmaxf(mx[d], v);
        }
    }
#pragma unroll
    for (int d = 0; d < 3; d++) {
#pragma unroll
        for (int o = 16; o > 0; o >>= 1) {
            mn[d] = fminf(mn[d], __shfl_xor_sync(0xffffffffu, mn[d], o));
            mx[d] = fmaxf(mx[d], __shfl_xor_sync(0xffffffffu, mx[d], o));
        }
    }
    if ((threadIdx.x & 31) == 0) {
#pragma unroll
        for (int d = 0; d < 3; d++) {
            atomicMin(&g_bbox_min[d], f2u_ord(mn[d]));
            atomicMax(&g_bbox_max[d], f2u_ord(mx[d]));
        }
    }
}

// ---------------------------------------------------------------------------
// K2: fused transpose, bbox-guarded — only texels reachable by the points
// are transposed. Out-of-range threads exit before any gmem load.
//   threads [0, VG)         : grid  [C,D,H,W] fp32 -> [D,H,W,C] fp16
//   threads [VG, VG + 3*V2) : planes [3,C,H,W] fp32 -> [3][H][W][C] fp16
// ---------------------------------------------------------------------------
__global__ void __launch_bounds__(256) transpose_all_kernel(
    const float* __restrict__ grid_in,
    const float* __restrict__ planes_in,
    const int* __restrict__ bound_p)
{
    const int VG = LRES * LRES * LRES;
    const int V2 = HRES * HRES;
    int t = blockIdx.x * blockDim.x + threadIdx.x;

    // normalized bbox (handles negative bound by re-sorting)
    float inv = 1.0f / get_bound(bound_p);
    float nmin[3], nmax[3];
#pragma unroll
    for (int d = 0; d < 3; d++) {
        float a = u2f_ord(g_bbox_min[d]) * inv;
        float b = u2f_ord(g_bbox_max[d]) * inv;
        nmin[d] = fminf(a, b);
        nmax[d] = fmaxf(a, b);
    }

    if (t < VG) {
        int v = t;
        int x = v & (LRES - 1);
        int y = (v >> 7) & (LRES - 1);
        int z = v >> 14;
        int lo, hi;
        coord_range(nmin[0], nmax[0], LRES, lo, hi);
        if (x < lo || x > hi) return;
        coord_range(nmin[1], nmax[1], LRES, lo, hi);
        if (y < lo || y > hi) return;
        coord_range(nmin[2], nmax[2], LRES, lo, hi);
        if (z < lo || z > hi) return;

        float4 a, b;
        a.x = __ldg(grid_in + 0 * VG + v);
        a.y = __ldg(grid_in + 1 * VG + v);
        a.z = __ldg(grid_in + 2 * VG + v);
        a.w = __ldg(grid_in + 3 * VG + v);
        b.x = __ldg(grid_in + 4 * VG + v);
        b.y = __ldg(grid_in + 5 * VG + v);
        b.z = __ldg(grid_in + 6 * VG + v);
        b.w = __ldg(grid_in + 7 * VG + v);
        reinterpret_cast<uint4*>(g_grid_h)[v] = pack8_half(a, b);
    } else {
        int u = t - VG;
        if (u >= 3 * V2) return;
        int p = u / V2;
        int v = u - p * V2;
        int w = v & (HRES - 1);
        int h = v >> 10;

        // plane d->coord map: p0 (W=x,H=y), p1 (W=y,H=z), p2 (W=z,H=x)
        int wd = p;              // W coord dim: 0,1,2
        int hd = (p + 1) % 3;    // H coord dim: 1,2,0
        int lo, hi;
        coord_range(nmin[wd], nmax[wd], HRES, lo, hi);
        if (w < lo || w > hi) return;
        coord_range(nmin[hd], nmax[hd], HRES, lo, hi);
        if (h < lo || h > hi) return;

        const float* base = planes_in + (size_t)p * NCH * V2 + v;
        float4 a, b;
        a.x = __ldg(base + 0 * V2);
        a.y = __ldg(base + 1 * V2);
        a.z = __ldg(base + 2 * V2);
        a.w = __ldg(base + 3 * V2);
        b.x = __ldg(base + 4 * V2);
        b.y = __ldg(base + 5 * V2);
        b.z = __ldg(base + 6 * V2);
        b.w = __ldg(base + 7 * V2);
        reinterpret_cast<uint4*>(g_planes_h)[u] = pack8_half(a, b);
    }
}

// ---------------------------------------------------------------------------
// K3: pair-lane gather (byte-identical logic to the 129.1 µs best).
// Lanes (2i, 2i+1) share point i; lane r handles W index x_r.
// 10 LDG.128/lane, half-exchange via 4 SHFL.BFLY, contiguous 16B store.
// ---------------------------------------------------------------------------
__global__ void __launch_bounds__(256) gather_kernel(
    const float* __restrict__ xyz,
    const int* __restrict__ bound_p,
    float* __restrict__ out,
    int N)
{
    int tid = blockIdx.x * blockDim.x + threadIdx.x;
    int n = tid >> 1;            // point index (2 lanes per point)
    int r = tid & 1;             // 0: low W index, 1: high W index
    if (n >= N) return;

    float inv = 1.0f / get_bound(bound_p);
    float x = __ldg(xyz + 3 * n + 0) * inv;
    float y = __ldg(xyz + 3 * n + 1) * inv;
    float z = __ldg(xyz + 3 * n + 2) * inv;

    const uint4* GT = reinterpret_cast<const uint4*>(g_grid_h);
    const uint4* PT = reinterpret_cast<const uint4*>(g_planes_h);

    int x0, x1, y0, y1, z0, z1;
    float wx, wy, wz;
    to_idx(x, LRES, x0, x1, wx);
    to_idx(y, LRES, y0, y1, wy);
    to_idx(z, LRES, z0, z1, wz);

    int xh0, xh1, yh0, yh1, zh0, zh1;
    float wxh, wyh, wzh;
    to_idx(x, HRES, xh0, xh1, wxh);
    to_idx(y, HRES, yh0, yh1, wyh);
    to_idx(z, HRES, zh0, zh1, wzh);

    int   gx  = r ? x1  : x0;   float wgx = r ? wx  : 1.0f - wx;
    int   p0x = r ? xh1 : xh0;  float w0x = r ? wxh : 1.0f - wxh;  // plane0 W = x
    int   p1y = r ? yh1 : yh0;  float w1y = r ? wyh : 1.0f - wyh;  // plane1 W = y
    int   p2z = r ? zh1 : zh0;  float w2z = r ? wzh : 1.0f - wzh;  // plane2 W = z

    #define GIDX(zz, yy) (((zz) * LRES + (yy)) * LRES + gx)
    uint4 g00 = __ldg(GT + GIDX(z0, y0));
    uint4 g01 = __ldg(GT + GIDX(z0, y1));
    uint4 g10 = __ldg(GT + GIDX(z1, y0));
    uint4 g11 = __ldg(GT + GIDX(z1, y1));
    #undef GIDX
    #define PIDX(p, hh, ww) ((p) * (HRES * HRES) + (hh) * HRES + (ww))
    uint4 pa0 = __ldg(PT + PIDX(0, yh0, p0x));
    uint4 pa1 = __ldg(PT + PIDX(0, yh1, p0x));
    uint4 pb0 = __ldg(PT + PIDX(1, zh0, p1y));
    uint4 pb1 = __ldg(PT + PIDX(1, zh1, p1y));
    uint4 pc0 = __ldg(PT + PIDX(2, xh0, p2z));
    uint4 pc1 = __ldg(PT + PIDX(2, xh1, p2z));
    #undef PIDX

    float acc[NCH];
#pragma unroll
    for (int c = 0; c < NCH; c++) acc[c] = 0.0f;

    {
        float uy = 1.0f - wy, uz = 1.0f - wz;
        acc_texel(acc, g00, uz * uy * wgx);
        acc_texel(acc, g01, uz * wy * wgx);
        acc_texel(acc, g10, wz * uy * wgx);
        acc_texel(acc, g11, wz * wy * wgx);
    }
    acc_texel(acc, pa0, (1.0f - wyh) * w0x);   // plane0: H = y
    acc_texel(acc, pa1, wyh * w0x);
    acc_texel(acc, pb0, (1.0f - wzh) * w1y);   // plane1: H = z
    acc_texel(acc, pb1, wzh * w1y);
    acc_texel(acc, pc0, (1.0f - wxh) * w2z);   // plane2: H = x
    acc_texel(acc, pc1, wxh * w2z);

    // half exchange: 4 SHFLs, each lane sends the half it doesn't keep
    unsigned mask = __activemask();
    float res[4];
#pragma unroll
    for (int c = 0; c < 4; c++) {
        float keep = r ? acc[c + 4] : acc[c];
        float send = r ? acc[c]     : acc[c + 4];
        res[c] = keep + __shfl_xor_sync(mask, send, 1);
    }

    reinterpret_cast<float4*>(out)[(size_t)n * 2 + r] =
        make_float4(res[0], res[1], res[2], res[3]);
}

extern "C" void kernel_launch(void* const* d_in, const int* in_sizes, int n_in,
                              void* d_out, int out_size) {
    const float* xyz   = (const float*)d_in[0];
    const int*   bound = (const int*)d_in[1];
    const float* Lg    = (const float*)d_in[2];
    const float* Hp    = (const float*)d_in[3];
    float* out = (float*)d_out;

    int N = in_sizes[0] / 3;

    bbox_init_kernel<<<1, 32>>>();
    bbox_kernel<<<512, 256>>>(xyz, N);

    const int VG = LRES * LRES * LRES;
    const int VT = VG + 3 * HRES * HRES;
    transpose_all_kernel<<<(VT + 255) / 256, 256>>>(Lg, Hp, bound);

    gather_kernel<<<(2 * N + 255) / 256, 256>>>(xyz, bound, out, N);
}